// round 7
// baseline (speedup 1.0000x reference)
#include <cuda_runtime.h>

#define NN     500000   // N_NODES upper bound
#define TB     256
#define NB     128      // dst bins
#define BSH    12       // bin shift: 4096 nodes per bin
#define BNODES 4096
#define BINCAP 150000   // slots per bin (E/NB ~ 130k expected)
#define OVCAP  (1<<21)  // overflow list capacity
#define CPB1   8        // CTAs per bin, deg/scatter1
#define CPB2   4        // CTAs per bin, scatter2 (32KB smem)
#define OVB    8        // extra blocks for overflow edges
#define EPC    4096     // edges per CTA in binscatter (16/thread)

// Scratch (no cudaMalloc allowed).
__device__ int    g_is64;        // 1 if edge_index is int64, 0 if int32
__device__ int    g_b1zero;      // 1 if b1 == 0 (scalar layer-2 path)
__device__ int    g_cursor[NB];  // bin allocation cursors (global slot)
__device__ int    g_ovf_cnt;
__device__ int2   g_bin[NB * BINCAP];  // binned (src,dst)
__device__ int2   g_ovf[OVCAP];
__device__ float  g_deg [NN];
__device__ float  g_dinv[NN];
__device__ float  g_v   [NN];    // dinv*x              (gather, layer 1)
__device__ float  g_s   [NN];    // layer-1 accumulator (init = self-loop)
__device__ float  g_val [NN];    // dinv*pre            (gather, layer 2 fast)
__device__ float  g_spos[NN];
__device__ float  g_sneg[NN];
__device__ float4 g_h2d [NN];    // fallback payload (b1 != 0)

// ---------------- probe + init ----------------
__global__ void k_probe_init(const void* ei, int E, int n, const float* __restrict__ b1) {
    int i = blockIdx.x * blockDim.x + threadIdx.x;
    if (i < n) g_deg[i] = 1.0f;                  // self-loop
    if (i < NB) g_cursor[i] = i * BINCAP;
    if (i == 0) g_ovf_cnt = 0;
    if (blockIdx.x == 0) {
        // dtype probe: as int64, genuine int64 indices are in [0,n).
        __shared__ int ok;
        if (threadIdx.x == 0) ok = 1;
        __syncthreads();
        const long long* p = (const long long*)ei;
        long long stride = E / blockDim.x;
        if (stride < 1) stride = 1;
        long long idx = (long long)threadIdx.x * stride;
        if (idx < E) {
            long long v = p[idx];
            if (v < 0 || v >= (long long)n) ok = 0;
        }
        __syncthreads();
        if (threadIdx.x == 0) {
            g_is64 = ok;
            g_b1zero = (b1[0] == 0.0f && b1[1] == 0.0f &&
                        b1[2] == 0.0f && b1[3] == 0.0f) ? 1 : 0;
        }
    }
}

// ---------------- binning pass ----------------
// Each CTA: 4096 consecutive edges (16/thread in registers), 3 phases:
// local smem histogram -> reserve global ranges -> write packed (src,dst).
__global__ void __launch_bounds__(TB) k_binscatter(const void* __restrict__ ei, int E, int n) {
    __shared__ int sh_hist[NB];
    __shared__ int sh_base[NB];
    int tid = threadIdx.x;
    int is64 = g_is64;
    long long base_e = (long long)blockIdx.x * EPC + (long long)tid * 16;
    bool fulltile = ((long long)(blockIdx.x + 1) * EPC <= E);

    int s[16], d[16];
    if (!is64 && fulltile && (E & 3) == 0) {
        const int4* sp = (const int4*)ei;
        const int4* dp = (const int4*)ei + (E >> 2);
        long long q = base_e >> 2;
#pragma unroll
        for (int p = 0; p < 4; p++) {
            int4 a = __ldcs(&sp[q + p]);
            int4 b = __ldcs(&dp[q + p]);
            s[p*4+0]=a.x; s[p*4+1]=a.y; s[p*4+2]=a.z; s[p*4+3]=a.w;
            d[p*4+0]=b.x; d[p*4+1]=b.y; d[p*4+2]=b.z; d[p*4+3]=b.w;
        }
    } else {
#pragma unroll
        for (int k = 0; k < 16; k++) {
            long long e = base_e + k;
            if (e < E) {
                if (is64) {
                    s[k] = (int)__ldcs(((const long long*)ei) + e);
                    d[k] = (int)__ldcs(((const long long*)ei) + e + E);
                } else {
                    s[k] = __ldcs(((const int*)ei) + e);
                    d[k] = __ldcs(((const int*)ei) + e + E);
                }
            } else { d[k] = -1; }
        }
    }
    // invalid-dst edges dropped (match previous guarded semantics)
#pragma unroll
    for (int k = 0; k < 16; k++)
        if ((unsigned)d[k] >= (unsigned)n) d[k] = -1;

    for (int j = tid; j < NB; j += TB) sh_hist[j] = 0;
    __syncthreads();
#pragma unroll
    for (int k = 0; k < 16; k++)
        if (d[k] >= 0) atomicAdd(&sh_hist[d[k] >> BSH], 1);
    __syncthreads();
    if (tid < NB) {
        int c = sh_hist[tid];
        int b = c ? atomicAdd(&g_cursor[tid], c) : 0;
        sh_base[tid] = b;
        sh_hist[tid] = 0;                       // reuse as local offset
    }
    __syncthreads();
#pragma unroll
    for (int k = 0; k < 16; k++) {
        if (d[k] >= 0) {
            int bin  = d[k] >> BSH;
            int off  = atomicAdd(&sh_hist[bin], 1);
            int slot = sh_base[bin] + off;
            if (slot < (bin + 1) * BINCAP) {
                g_bin[slot] = make_int2(s[k], d[k]);
            } else {
                int o = atomicAdd(&g_ovf_cnt, 1);
                if (o < OVCAP) g_ovf[o] = make_int2(s[k], d[k]);
            }
        }
    }
}

// ---------------- binned slice helper ----------------
__device__ __forceinline__ void bin_slice(int bin, int sub, int cpb, int& lo, int& hi) {
    int cnt = g_cursor[bin] - bin * BINCAP;
    if (cnt > BINCAP) cnt = BINCAP;
    if (cnt < 0) cnt = 0;
    lo = (int)((long long)cnt * sub / cpb);
    hi = (int)((long long)cnt * (sub + 1) / cpb);
}

// ---------------- binned degree ----------------
__global__ void __launch_bounds__(TB) k_deg_b(int n) {
    if (blockIdx.x >= NB * CPB1) {              // overflow edges: direct atomics
        int cnt = min(g_ovf_cnt, OVCAP);
        for (int i = (blockIdx.x - NB * CPB1) * TB + threadIdx.x; i < cnt; i += OVB * TB)
            atomicAdd(&g_deg[g_ovf[i].y], 1.0f);
        return;
    }
    int bin = blockIdx.x / CPB1, sub = blockIdx.x % CPB1;
    int lo, hi; bin_slice(bin, sub, CPB1, lo, hi);
    __shared__ float acc[BNODES];
    for (int j = threadIdx.x; j < BNODES; j += TB) acc[j] = 0.0f;
    __syncthreads();
    const int2* bp = g_bin + (long long)bin * BINCAP;
    for (int i = lo + threadIdx.x; i < hi; i += TB) {
        int2 e = __ldg(&bp[i]);
        atomicAdd(&acc[e.y & (BNODES - 1)], 1.0f);
    }
    __syncthreads();
    int nodebase = bin << BSH;
    for (int j = threadIdx.x; j < BNODES; j += TB) {
        float v = acc[j];
        int node = nodebase + j;
        if (v != 0.0f && node < n) atomicAdd(&g_deg[node], v);
    }
}

// ---------------- node kernels ----------------
__global__ void k_dinv(const float* __restrict__ x, int n) {
    int i = blockIdx.x * blockDim.x + threadIdx.x;
    if (i < n) {
        float di = rsqrtf(g_deg[i]);
        g_dinv[i] = di;
        float v = di * x[i];
        g_v[i] = v;
        g_s[i] = v;                              // self-loop, layer 1
    }
}

__global__ void k_mid(const float* __restrict__ W1, const float* __restrict__ b1,
                      const float* __restrict__ W2,
                      float4* __restrict__ out, int n) {
    int i = blockIdx.x * blockDim.x + threadIdx.x;
    if (i >= n) return;
    float di  = g_dinv[i];
    float pre = di * g_s[i];
    float val = di * pre;
    g_val [i] = val;
    g_spos[i] = fmaxf(val, 0.0f);                // self-loop, layer 2
    g_sneg[i] = fmaxf(-val, 0.0f);
    if (!g_b1zero) {
        float h[4];
#pragma unroll
        for (int c = 0; c < 4; c++)
            h[c] = fmaxf(fmaf(pre, __ldg(&W1[c]), __ldg(&b1[c])), 0.0f);
        float4 v;
        v.x = di * (h[0]*__ldg(&W2[0]) + h[1]*__ldg(&W2[4]) + h[2]*__ldg(&W2[8])  + h[3]*__ldg(&W2[12]));
        v.y = di * (h[0]*__ldg(&W2[1]) + h[1]*__ldg(&W2[5]) + h[2]*__ldg(&W2[9])  + h[3]*__ldg(&W2[13]));
        v.z = di * (h[0]*__ldg(&W2[2]) + h[1]*__ldg(&W2[6]) + h[2]*__ldg(&W2[10]) + h[3]*__ldg(&W2[14]));
        v.w = di * (h[0]*__ldg(&W2[3]) + h[1]*__ldg(&W2[7]) + h[2]*__ldg(&W2[11]) + h[3]*__ldg(&W2[15]));
        g_h2d[i] = v;
        out[i]   = v;
    }
}

__global__ void k_final(const float* __restrict__ W1, const float* __restrict__ W2,
                        const float* __restrict__ b2,
                        float4* __restrict__ out, int n) {
    int i = blockIdx.x * blockDim.x + threadIdx.x;
    if (i >= n) return;
    float di = g_dinv[i];
    if (g_b1zero) {
        float gp[4], gn[4];
#pragma unroll
        for (int k = 0; k < 4; k++) {
            float w = __ldg(&W1[k]);
            gp[k] = fmaxf(w, 0.0f);
            gn[k] = fmaxf(-w, 0.0f);
        }
        float sp = g_spos[i], sn = g_sneg[i];
        float o[4];
#pragma unroll
        for (int c = 0; c < 4; c++) {
            float up = gp[0]*__ldg(&W2[0*4+c]) + gp[1]*__ldg(&W2[1*4+c])
                     + gp[2]*__ldg(&W2[2*4+c]) + gp[3]*__ldg(&W2[3*4+c]);
            float un = gn[0]*__ldg(&W2[0*4+c]) + gn[1]*__ldg(&W2[1*4+c])
                     + gn[2]*__ldg(&W2[2*4+c]) + gn[3]*__ldg(&W2[3*4+c]);
            o[c] = fmaf(di, sp*up + sn*un, __ldg(&b2[c]));
        }
        out[i] = make_float4(o[0], o[1], o[2], o[3]);
    } else {
        float4 o = out[i];
        out[i] = make_float4(fmaf(di, o.x, __ldg(&b2[0])),
                             fmaf(di, o.y, __ldg(&b2[1])),
                             fmaf(di, o.z, __ldg(&b2[2])),
                             fmaf(di, o.w, __ldg(&b2[3])));
    }
}

// ---------------- binned scatter, layer 1 ----------------
__global__ void __launch_bounds__(TB) k_scatter1_b(int n) {
    if (blockIdx.x >= NB * CPB1) {
        int cnt = min(g_ovf_cnt, OVCAP);
        for (int i = (blockIdx.x - NB * CPB1) * TB + threadIdx.x; i < cnt; i += OVB * TB) {
            int2 e = g_ovf[i];
            if ((unsigned)e.x < (unsigned)n)
                atomicAdd(&g_s[e.y], __ldg(&g_v[e.x]));
        }
        return;
    }
    int bin = blockIdx.x / CPB1, sub = blockIdx.x % CPB1;
    int lo, hi; bin_slice(bin, sub, CPB1, lo, hi);
    __shared__ float acc[BNODES];
    for (int j = threadIdx.x; j < BNODES; j += TB) acc[j] = 0.0f;
    __syncthreads();
    const int2* bp = g_bin + (long long)bin * BINCAP;
    for (int i = lo + threadIdx.x; i < hi; i += TB) {
        int2 e = __ldg(&bp[i]);
        if ((unsigned)e.x < (unsigned)n)
            atomicAdd(&acc[e.y & (BNODES - 1)], __ldg(&g_v[e.x]));
    }
    __syncthreads();
    int nodebase = bin << BSH;
    for (int j = threadIdx.x; j < BNODES; j += TB) {
        float v = acc[j];
        int node = nodebase + j;
        if (v != 0.0f && node < n) atomicAdd(&g_s[node], v);
    }
}

// ---------------- binned scatter, layer 2 ----------------
__global__ void __launch_bounds__(TB) k_scatter2_b(float4* __restrict__ out, int n) {
    int fast = g_b1zero;
    if (blockIdx.x >= NB * CPB2) {               // overflow edges
        int cnt = min(g_ovf_cnt, OVCAP);
        for (int i = (blockIdx.x - NB * CPB2) * TB + threadIdx.x; i < cnt; i += OVB * TB) {
            int2 e = g_ovf[i];
            if ((unsigned)e.x < (unsigned)n) {
                if (fast) {
                    float v = __ldg(&g_val[e.x]);
                    if (v >= 0.0f) atomicAdd(&g_spos[e.y], v);
                    else           atomicAdd(&g_sneg[e.y], -v);
                } else {
                    float4 m = __ldg(&g_h2d[e.x]);
                    float* p = reinterpret_cast<float*>(&out[e.y]);
                    asm volatile("red.global.add.v4.f32 [%0], {%1,%2,%3,%4};"
                                 :: "l"(p), "f"(m.x), "f"(m.y), "f"(m.z), "f"(m.w)
                                 : "memory");
                }
            }
        }
        return;
    }
    int bin = blockIdx.x / CPB2, sub = blockIdx.x % CPB2;
    int lo, hi; bin_slice(bin, sub, CPB2, lo, hi);
    const int2* bp = g_bin + (long long)bin * BINCAP;
    if (fast) {
        __shared__ float accp[BNODES];
        __shared__ float accn[BNODES];
        for (int j = threadIdx.x; j < BNODES; j += TB) { accp[j] = 0.0f; accn[j] = 0.0f; }
        __syncthreads();
        for (int i = lo + threadIdx.x; i < hi; i += TB) {
            int2 e = __ldg(&bp[i]);
            if ((unsigned)e.x < (unsigned)n) {
                float v = __ldg(&g_val[e.x]);
                int j = e.y & (BNODES - 1);
                if (v >= 0.0f) atomicAdd(&accp[j], v);
                else           atomicAdd(&accn[j], -v);
            }
        }
        __syncthreads();
        int nodebase = bin << BSH;
        for (int j = threadIdx.x; j < BNODES; j += TB) {
            int node = nodebase + j;
            if (node < n) {
                float p = accp[j], q = accn[j];
                if (p != 0.0f) atomicAdd(&g_spos[node], p);
                if (q != 0.0f) atomicAdd(&g_sneg[node], q);
            }
        }
    } else {                                     // fallback: direct red.v4
        for (int i = lo + threadIdx.x; i < hi; i += TB) {
            int2 e = __ldg(&bp[i]);
            if ((unsigned)e.x < (unsigned)n) {
                float4 m = __ldg(&g_h2d[e.x]);
                float* p = reinterpret_cast<float*>(&out[e.y]);
                asm volatile("red.global.add.v4.f32 [%0], {%1,%2,%3,%4};"
                             :: "l"(p), "f"(m.x), "f"(m.y), "f"(m.z), "f"(m.w)
                             : "memory");
            }
        }
    }
}

// ---------------- launch ----------------
extern "C" void kernel_launch(void* const* d_in, const int* in_sizes, int n_in,
                              void* d_out, int out_size) {
    const float* x  = (const float*)d_in[0];
    const void*  ei = d_in[1];                 // [2, E], int32 or int64
    const float* W1 = (const float*)d_in[2];
    const float* b1 = (const float*)d_in[3];
    const float* W2 = (const float*)d_in[4];
    const float* b2 = (const float*)d_in[5];
    float4* out = (float4*)d_out;

    int n = in_sizes[0];
    int E = in_sizes[1] / 2;

    int nb_node = (n + TB - 1) / TB;
    int nb_binsc = (E + EPC - 1) / EPC;

    k_probe_init <<<nb_node, TB>>>(ei, E, n, b1);
    k_binscatter <<<nb_binsc, TB>>>(ei, E, n);
    k_deg_b      <<<NB * CPB1 + OVB, TB>>>(n);
    k_dinv       <<<nb_node, TB>>>(x, n);
    k_scatter1_b <<<NB * CPB1 + OVB, TB>>>(n);
    k_mid        <<<nb_node, TB>>>(W1, b1, W2, out, n);
    k_scatter2_b <<<NB * CPB2 + OVB, TB>>>(out, n);
    k_final      <<<nb_node, TB>>>(W1, W2, b2, out, n);
}

// round 8
// speedup vs baseline: 1.2992x; 1.2992x over previous
#include <cuda_runtime.h>

#define NN 500000   // N_NODES upper bound
#define TB 256
#define EPT 4       // edges per thread in edge kernels

// Scratch (no cudaMalloc allowed).
__device__ int    g_is64;        // 1 if edge_index is int64, 0 if int32
__device__ int    g_b1zero;      // 1 if b1 == 0 (enables scalar layer-2 path)
__device__ float  g_deg [NN];    // degree (float; exact for counts < 2^24)
__device__ float  g_dinv[NN];    // deg^{-1/2}
__device__ float  g_v   [NN];    // dinv[i] * x[i]          (gather source, layer 1)
__device__ float  g_s   [NN];    // layer-1 accumulator (init = self-loop term)
__device__ float  g_val [NN];    // dinv[i]^2 * s[i] = dinv*pre  (gather, layer 2 fast path)
__device__ float2 g_sb  [NN];    // (Σ max(val,0), Σ max(-val,0)) at dst, interleaved
__device__ float4 g_h2d [NN];    // dinv[i]*(relu(pre)@W2)  (gather, fallback path)

// ---------------- probe + degree init (fused) ----------------
__global__ void k_probe_init(const void* ei, int E, int n, const float* __restrict__ b1) {
    int i = blockIdx.x * blockDim.x + threadIdx.x;
    if (i < n) g_deg[i] = 1.0f;              // self-loop
    if (blockIdx.x == 0) {
        // dtype probe: as int64, genuine int64 indices are in [0,n).
        // int32 misread as int64 gives lo + hi*2^32, out of range unless hi==0.
        __shared__ int ok;
        if (threadIdx.x == 0) ok = 1;
        __syncthreads();
        const long long* p = (const long long*)ei;
        long long stride = E / blockDim.x;
        if (stride < 1) stride = 1;
        long long idx = (long long)threadIdx.x * stride;
        if (idx < E) {   // first E int64 slots in-bounds under BOTH interpretations
            long long v = p[idx];
            if (v < 0 || v >= (long long)n) ok = 0;
        }
        __syncthreads();
        if (threadIdx.x == 0) {
            g_is64 = ok;
            g_b1zero = (b1[0] == 0.0f && b1[1] == 0.0f &&
                        b1[2] == 0.0f && b1[3] == 0.0f) ? 1 : 0;
        }
    }
}

// ---------------- node kernels ----------------

__global__ void k_dinv(const float* __restrict__ x, int n) {
    int i = blockIdx.x * blockDim.x + threadIdx.x;
    if (i < n) {
        float di = rsqrtf(g_deg[i]);         // deg >= 1 always (self-loop)
        g_dinv[i] = di;
        float v = di * x[i];
        g_v[i] = v;
        g_s[i] = v;                          // self-loop contribution, layer 1
    }
}

__global__ void k_mid(const float* __restrict__ W1, const float* __restrict__ b1,
                      const float* __restrict__ W2,
                      float4* __restrict__ out, int n) {
    int i = blockIdx.x * blockDim.x + threadIdx.x;
    if (i >= n) return;
    float di  = g_dinv[i];
    float pre = di * g_s[i];
    float val = di * pre;
    g_val[i] = val;
    g_sb [i] = make_float2(fmaxf(val, 0.0f), fmaxf(-val, 0.0f));  // self-loop, layer 2
    if (!g_b1zero) {                         // fallback representation (b1 != 0)
        float h[4];
#pragma unroll
        for (int c = 0; c < 4; c++)
            h[c] = fmaxf(fmaf(pre, __ldg(&W1[c]), __ldg(&b1[c])), 0.0f);
        float4 v;
        v.x = di * (h[0]*__ldg(&W2[0]) + h[1]*__ldg(&W2[4]) + h[2]*__ldg(&W2[8])  + h[3]*__ldg(&W2[12]));
        v.y = di * (h[0]*__ldg(&W2[1]) + h[1]*__ldg(&W2[5]) + h[2]*__ldg(&W2[9])  + h[3]*__ldg(&W2[13]));
        v.z = di * (h[0]*__ldg(&W2[2]) + h[1]*__ldg(&W2[6]) + h[2]*__ldg(&W2[10]) + h[3]*__ldg(&W2[14]));
        v.w = di * (h[0]*__ldg(&W2[3]) + h[1]*__ldg(&W2[7]) + h[2]*__ldg(&W2[11]) + h[3]*__ldg(&W2[15]));
        g_h2d[i] = v;
        out[i]   = v;
    }
}

__global__ void k_final(const float* __restrict__ W1, const float* __restrict__ W2,
                        const float* __restrict__ b2,
                        float4* __restrict__ out, int n) {
    int i = blockIdx.x * blockDim.x + threadIdx.x;
    if (i >= n) return;
    float di = g_dinv[i];
    if (g_b1zero) {
        float gp[4], gn[4];
#pragma unroll
        for (int k = 0; k < 4; k++) {
            float w = __ldg(&W1[k]);
            gp[k] = fmaxf(w, 0.0f);
            gn[k] = fmaxf(-w, 0.0f);
        }
        float2 sb = g_sb[i];
        float o[4];
#pragma unroll
        for (int c = 0; c < 4; c++) {
            float up = gp[0]*__ldg(&W2[0*4+c]) + gp[1]*__ldg(&W2[1*4+c])
                     + gp[2]*__ldg(&W2[2*4+c]) + gp[3]*__ldg(&W2[3*4+c]);
            float un = gn[0]*__ldg(&W2[0*4+c]) + gn[1]*__ldg(&W2[1*4+c])
                     + gn[2]*__ldg(&W2[2*4+c]) + gn[3]*__ldg(&W2[3*4+c]);
            o[c] = fmaf(di, sb.x*up + sb.y*un, __ldg(&b2[c]));
        }
        out[i] = make_float4(o[0], o[1], o[2], o[3]);
    } else {
        float4 o = out[i];
        out[i] = make_float4(fmaf(di, o.x, __ldg(&b2[0])),
                             fmaf(di, o.y, __ldg(&b2[1])),
                             fmaf(di, o.z, __ldg(&b2[2])),
                             fmaf(di, o.w, __ldg(&b2[3])));
    }
}

// ---------------- edge kernels ----------------
// Edge-index loads use __ldcs (evict-first streaming) so the edge stream does
// not evict the L2-resident node arrays.

__device__ __forceinline__ int load_idx_cs(const void* ei, long long e, int is64) {
    if (is64) return (int)__ldcs(((const long long*)ei) + e);
    return __ldcs(((const int*)ei) + e);
}

__global__ void __launch_bounds__(TB) k_deg(const void* __restrict__ ei, int E, int n) {
    int is64 = g_is64;
    int e0 = blockIdx.x * blockDim.x * EPT + threadIdx.x;
    for (int k = 0; k < EPT; k++) {
        int e = e0 + k * blockDim.x;
        if (e < E) {
            int d = load_idx_cs(ei, (long long)e + E, is64);
            if ((unsigned)d < (unsigned)n) atomicAdd(&g_deg[d], 1.0f);
        }
    }
}

__global__ void __launch_bounds__(TB) k_scatter1(const void* __restrict__ ei, int E, int n) {
    int is64 = g_is64;
    int e0 = blockIdx.x * blockDim.x * EPT + threadIdx.x;
    for (int k = 0; k < EPT; k++) {
        int e = e0 + k * blockDim.x;
        if (e < E) {
            int s = load_idx_cs(ei, e, is64);
            int d = load_idx_cs(ei, (long long)e + E, is64);
            if ((unsigned)s < (unsigned)n && (unsigned)d < (unsigned)n)
                atomicAdd(&g_s[d], __ldg(&g_v[s]));
        }
    }
}

__global__ void __launch_bounds__(TB) k_scatter2(const void* __restrict__ ei,
                                                 float4* __restrict__ out, int E, int n) {
    int is64 = g_is64;
    int fast = g_b1zero;
    int e0 = blockIdx.x * blockDim.x * EPT + threadIdx.x;
    for (int k = 0; k < EPT; k++) {
        int e = e0 + k * blockDim.x;
        if (e < E) {
            int s = load_idx_cs(ei, e, is64);
            int d = load_idx_cs(ei, (long long)e + E, is64);
            if ((unsigned)s < (unsigned)n && (unsigned)d < (unsigned)n) {
                if (fast) {
                    // Branch-free: one red.v2 carries (pos, neg); the inactive
                    // component adds +0.0f (exact). Halves SM-side RED issue
                    // vs the divergent two-branch form.
                    float v  = __ldg(&g_val[s]);
                    float vp = fmaxf(v, 0.0f);
                    float vn = fmaxf(-v, 0.0f);
                    float* p = reinterpret_cast<float*>(&g_sb[d]);
                    asm volatile("red.global.add.v2.f32 [%0], {%1,%2};"
                                 :: "l"(p), "f"(vp), "f"(vn)
                                 : "memory");
                } else {
                    float4 m = __ldg(&g_h2d[s]);
                    float* p = reinterpret_cast<float*>(&out[d]);
                    asm volatile("red.global.add.v4.f32 [%0], {%1,%2,%3,%4};"
                                 :: "l"(p), "f"(m.x), "f"(m.y), "f"(m.z), "f"(m.w)
                                 : "memory");
                }
            }
        }
    }
}

// ---------------- launch ----------------

extern "C" void kernel_launch(void* const* d_in, const int* in_sizes, int n_in,
                              void* d_out, int out_size) {
    const float* x  = (const float*)d_in[0];
    const void*  ei = d_in[1];                 // [2, E], int32 or int64
    const float* W1 = (const float*)d_in[2];
    const float* b1 = (const float*)d_in[3];
    const float* W2 = (const float*)d_in[4];
    const float* b2 = (const float*)d_in[5];
    float4* out = (float4*)d_out;

    int n = in_sizes[0];            // N nodes (C_in = 1)
    int E = in_sizes[1] / 2;        // element count is dtype-independent

    int nb_node = (n + TB - 1) / TB;
    int nb_edge = (E + TB * EPT - 1) / (TB * EPT);

    k_probe_init <<<nb_node, TB>>>(ei, E, n, b1);       // 1
    k_deg        <<<nb_edge, TB>>>(ei, E, n);           // 2
    k_dinv       <<<nb_node, TB>>>(x, n);               // 3
    k_scatter1   <<<nb_edge, TB>>>(ei, E, n);           // 4
    k_mid        <<<nb_node, TB>>>(W1, b1, W2, out, n); // 5
    k_scatter2   <<<nb_edge, TB>>>(ei, out, E, n);      // 6
    k_final      <<<nb_node, TB>>>(W1, W2, b2, out, n); // 7
}

// round 9
// speedup vs baseline: 1.3012x; 1.0016x over previous
#include <cuda_runtime.h>

#define NN 500000   // N_NODES upper bound
#define TB 256
#define EPT 4       // edges per thread in edge kernels

// Scratch (no cudaMalloc allowed).
__device__ int    g_is64;        // 1 if edge_index is int64, 0 if int32
__device__ int    g_b1zero;      // 1 if b1 == 0 (enables scalar layer-2 path)
__device__ float  g_deg [NN];    // degree (float; exact for counts < 2^24)
__device__ float  g_dinv[NN];    // deg^{-1/2}
__device__ float  g_v   [NN];    // dinv[i] * x[i]          (gather source, layer 1)
__device__ float  g_s   [NN];    // layer-1 accumulator (init = self-loop term)
__device__ float  g_val [NN];    // dinv[i]^2 * s[i] = dinv*pre  (gather, layer 2 fast path)
__device__ float2 g_sb  [NN];    // (Σ max(val,0), Σ max(-val,0)) at dst, interleaved
__device__ float4 g_h2d [NN];    // dinv[i]*(relu(pre)@W2)  (gather, fallback path)

// ---------------- probe + degree init (fused) ----------------
__global__ void k_probe_init(const void* ei, int E, int n, const float* __restrict__ b1) {
    int i = blockIdx.x * blockDim.x + threadIdx.x;
    if (i < n) g_deg[i] = 1.0f;              // self-loop
    if (blockIdx.x == 0) {
        // dtype probe: as int64, genuine int64 indices are in [0,n).
        // int32 misread as int64 gives lo + hi*2^32, out of range unless hi==0.
        __shared__ int ok;
        if (threadIdx.x == 0) ok = 1;
        __syncthreads();
        const long long* p = (const long long*)ei;
        long long stride = E / blockDim.x;
        if (stride < 1) stride = 1;
        long long idx = (long long)threadIdx.x * stride;
        if (idx < E) {   // first E int64 slots in-bounds under BOTH interpretations
            long long v = p[idx];
            if (v < 0 || v >= (long long)n) ok = 0;
        }
        __syncthreads();
        if (threadIdx.x == 0) {
            g_is64 = ok;
            g_b1zero = (b1[0] == 0.0f && b1[1] == 0.0f &&
                        b1[2] == 0.0f && b1[3] == 0.0f) ? 1 : 0;
        }
    }
}

// ---------------- node kernels ----------------

__global__ void k_dinv(const float* __restrict__ x, int n) {
    int i = blockIdx.x * blockDim.x + threadIdx.x;
    if (i < n) {
        float di = rsqrtf(g_deg[i]);         // deg >= 1 always (self-loop)
        g_dinv[i] = di;
        float v = di * x[i];
        g_v[i] = v;
        g_s[i] = v;                          // self-loop contribution, layer 1
    }
}

__global__ void k_mid(const float* __restrict__ W1, const float* __restrict__ b1,
                      const float* __restrict__ W2,
                      float4* __restrict__ out, int n) {
    int i = blockIdx.x * blockDim.x + threadIdx.x;
    if (i >= n) return;
    float di  = g_dinv[i];
    float pre = di * g_s[i];
    float val = di * pre;
    g_val[i] = val;
    g_sb [i] = make_float2(fmaxf(val, 0.0f), fmaxf(-val, 0.0f));  // self-loop, layer 2
    if (!g_b1zero) {                         // fallback representation (b1 != 0)
        float h[4];
#pragma unroll
        for (int c = 0; c < 4; c++)
            h[c] = fmaxf(fmaf(pre, __ldg(&W1[c]), __ldg(&b1[c])), 0.0f);
        float4 v;
        v.x = di * (h[0]*__ldg(&W2[0]) + h[1]*__ldg(&W2[4]) + h[2]*__ldg(&W2[8])  + h[3]*__ldg(&W2[12]));
        v.y = di * (h[0]*__ldg(&W2[1]) + h[1]*__ldg(&W2[5]) + h[2]*__ldg(&W2[9])  + h[3]*__ldg(&W2[13]));
        v.z = di * (h[0]*__ldg(&W2[2]) + h[1]*__ldg(&W2[6]) + h[2]*__ldg(&W2[10]) + h[3]*__ldg(&W2[14]));
        v.w = di * (h[0]*__ldg(&W2[3]) + h[1]*__ldg(&W2[7]) + h[2]*__ldg(&W2[11]) + h[3]*__ldg(&W2[15]));
        g_h2d[i] = v;
        out[i]   = v;
    }
}

__global__ void k_final(const float* __restrict__ W1, const float* __restrict__ W2,
                        const float* __restrict__ b2,
                        float4* __restrict__ out, int n) {
    int i = blockIdx.x * blockDim.x + threadIdx.x;
    if (i >= n) return;
    float di = g_dinv[i];
    if (g_b1zero) {
        float gp[4], gn[4];
#pragma unroll
        for (int k = 0; k < 4; k++) {
            float w = __ldg(&W1[k]);
            gp[k] = fmaxf(w, 0.0f);
            gn[k] = fmaxf(-w, 0.0f);
        }
        float2 sb = g_sb[i];
        float o[4];
#pragma unroll
        for (int c = 0; c < 4; c++) {
            float up = gp[0]*__ldg(&W2[0*4+c]) + gp[1]*__ldg(&W2[1*4+c])
                     + gp[2]*__ldg(&W2[2*4+c]) + gp[3]*__ldg(&W2[3*4+c]);
            float un = gn[0]*__ldg(&W2[0*4+c]) + gn[1]*__ldg(&W2[1*4+c])
                     + gn[2]*__ldg(&W2[2*4+c]) + gn[3]*__ldg(&W2[3*4+c]);
            o[c] = fmaf(di, sb.x*up + sb.y*un, __ldg(&b2[c]));
        }
        out[i] = make_float4(o[0], o[1], o[2], o[3]);
    } else {
        float4 o = out[i];
        out[i] = make_float4(fmaf(di, o.x, __ldg(&b2[0])),
                             fmaf(di, o.y, __ldg(&b2[1])),
                             fmaf(di, o.z, __ldg(&b2[2])),
                             fmaf(di, o.w, __ldg(&b2[3])));
    }
}

// ---------------- edge kernels ----------------

__device__ __forceinline__ int load_idx_cs(const void* ei, long long e, int is64) {
    if (is64) return (int)__ldcs(((const long long*)ei) + e);
    return __ldcs(((const int*)ei) + e);
}

// Degree pass: only 2 LSU ops/edge (dst LDG + REDG) -> plausibly LSU-issue
// bound. Vector fast path loads 4 consecutive dst with ONE int4 LDG
// (1.25 LSU ops/edge, -37% issue).
__global__ void __launch_bounds__(TB) k_deg(const void* __restrict__ ei, int E, int n) {
    int vec = (!g_is64) && ((E & 3) == 0);
    if (vec) {
        int t = blockIdx.x * blockDim.x + threadIdx.x;
        if (t * 4 >= E) return;
        const int4* dst4 = (const int4*)ei + (E >> 2);
        int4 d4 = __ldcs(&dst4[t]);
        if ((unsigned)d4.x < (unsigned)n) atomicAdd(&g_deg[d4.x], 1.0f);
        if ((unsigned)d4.y < (unsigned)n) atomicAdd(&g_deg[d4.y], 1.0f);
        if ((unsigned)d4.z < (unsigned)n) atomicAdd(&g_deg[d4.z], 1.0f);
        if ((unsigned)d4.w < (unsigned)n) atomicAdd(&g_deg[d4.w], 1.0f);
    } else {
        int is64 = g_is64;
        int e0 = blockIdx.x * blockDim.x * EPT + threadIdx.x;
        for (int k = 0; k < EPT; k++) {
            int e = e0 + k * blockDim.x;
            if (e < E) {
                int d = load_idx_cs(ei, (long long)e + E, is64);
                if ((unsigned)d < (unsigned)n) atomicAdd(&g_deg[d], 1.0f);
            }
        }
    }
}

__global__ void __launch_bounds__(TB) k_scatter1(const void* __restrict__ ei, int E, int n) {
    int is64 = g_is64;
    int e0 = blockIdx.x * blockDim.x * EPT + threadIdx.x;
    for (int k = 0; k < EPT; k++) {
        int e = e0 + k * blockDim.x;
        if (e < E) {
            int s = load_idx_cs(ei, e, is64);
            int d = load_idx_cs(ei, (long long)e + E, is64);
            if ((unsigned)s < (unsigned)n && (unsigned)d < (unsigned)n)
                atomicAdd(&g_s[d], __ldg(&g_v[s]));
        }
    }
}

__global__ void __launch_bounds__(TB) k_scatter2(const void* __restrict__ ei,
                                                 float4* __restrict__ out, int E, int n) {
    int is64 = g_is64;
    int fast = g_b1zero;
    int e0 = blockIdx.x * blockDim.x * EPT + threadIdx.x;
    for (int k = 0; k < EPT; k++) {
        int e = e0 + k * blockDim.x;
        if (e < E) {
            int s = load_idx_cs(ei, e, is64);
            int d = load_idx_cs(ei, (long long)e + E, is64);
            if ((unsigned)s < (unsigned)n && (unsigned)d < (unsigned)n) {
                if (fast) {
                    // Branch-free: one red.v2 carries (pos, neg); inactive
                    // component adds +0.0f (exact).
                    float v  = __ldg(&g_val[s]);
                    float vp = fmaxf(v, 0.0f);
                    float vn = fmaxf(-v, 0.0f);
                    float* p = reinterpret_cast<float*>(&g_sb[d]);
                    asm volatile("red.global.add.v2.f32 [%0], {%1,%2};"
                                 :: "l"(p), "f"(vp), "f"(vn)
                                 : "memory");
                } else {
                    float4 m = __ldg(&g_h2d[s]);
                    float* p = reinterpret_cast<float*>(&out[d]);
                    asm volatile("red.global.add.v4.f32 [%0], {%1,%2,%3,%4};"
                                 :: "l"(p), "f"(m.x), "f"(m.y), "f"(m.z), "f"(m.w)
                                 : "memory");
                }
            }
        }
    }
}

// ---------------- launch ----------------

extern "C" void kernel_launch(void* const* d_in, const int* in_sizes, int n_in,
                              void* d_out, int out_size) {
    const float* x  = (const float*)d_in[0];
    const void*  ei = d_in[1];                 // [2, E], int32 or int64
    const float* W1 = (const float*)d_in[2];
    const float* b1 = (const float*)d_in[3];
    const float* W2 = (const float*)d_in[4];
    const float* b2 = (const float*)d_in[5];
    float4* out = (float4*)d_out;

    int n = in_sizes[0];            // N nodes (C_in = 1)
    int E = in_sizes[1] / 2;        // element count is dtype-independent

    int nb_node = (n + TB - 1) / TB;
    int nb_edge = (E + TB * EPT - 1) / (TB * EPT);

    k_probe_init <<<nb_node, TB>>>(ei, E, n, b1);       // 1
    k_deg        <<<nb_edge, TB>>>(ei, E, n);           // 2 (vec path uses 1/4 the threads' loads)
    k_dinv       <<<nb_node, TB>>>(x, n);               // 3
    k_scatter1   <<<nb_edge, TB>>>(ei, E, n);           // 4
    k_mid        <<<nb_node, TB>>>(W1, b1, W2, out, n); // 5
    k_scatter2   <<<nb_edge, TB>>>(ei, out, E, n);      // 6
    k_final      <<<nb_node, TB>>>(W1, W2, b2, out, n); // 7
}